// round 3
// baseline (speedup 1.0000x reference)
#include <cuda_runtime.h>

#define HH 16
#define NN 8192
#define DD 64
#define WW 128
#define TS 64
#define NEGINF (-1e30f)

// Pooled K/V scratch (allocation-free: __device__ globals)
__device__ float g_k1[HH * 1024 * DD];
__device__ float g_v1[HH * 1024 * DD];
__device__ float g_k2[HH * 128 * DD];
__device__ float g_v2[HH * 128 * DD];
__device__ float g_k3[HH * 16 * DD];
__device__ float g_v3[HH * 16 * DD];

// ---------------- pooling kernels ----------------
__global__ void pool1_kernel(const float* __restrict__ k, const float* __restrict__ v) {
    int idx = blockIdx.x * blockDim.x + threadIdx.x;
    if (idx >= HH * 1024 * DD) return;
    int dd = idx & (DD - 1);
    int c  = (idx / DD) & 1023;
    int h  = idx / (DD * 1024);
    const float* ks = k + ((size_t)h * NN + (size_t)c * 8) * DD + dd;
    const float* vs = v + ((size_t)h * NN + (size_t)c * 8) * DD + dd;
    float sk = 0.f, sv = 0.f;
#pragma unroll
    for (int r = 0; r < 8; r++) { sk += ks[r * DD]; sv += vs[r * DD]; }
    g_k1[idx] = sk * 0.125f;
    g_v1[idx] = sv * 0.125f;
}

__global__ void pool2_kernel() {
    int idx = blockIdx.x * blockDim.x + threadIdx.x;
    if (idx >= HH * 128 * DD) return;
    int dd = idx & (DD - 1);
    int c  = (idx / DD) & 127;
    int h  = idx / (DD * 128);
    const float* ks = g_k1 + ((size_t)h * 1024 + (size_t)c * 8) * DD + dd;
    const float* vs = g_v1 + ((size_t)h * 1024 + (size_t)c * 8) * DD + dd;
    float sk = 0.f, sv = 0.f;
#pragma unroll
    for (int r = 0; r < 8; r++) { sk += ks[r * DD]; sv += vs[r * DD]; }
    g_k2[idx] = sk * 0.125f;
    g_v2[idx] = sv * 0.125f;
}

__global__ void pool3_kernel() {
    int idx = blockIdx.x * blockDim.x + threadIdx.x;
    if (idx >= HH * 16 * DD) return;
    int dd = idx & (DD - 1);
    int c  = (idx / DD) & 15;
    int h  = idx / (DD * 16);
    const float* ks = g_k2 + ((size_t)h * 128 + (size_t)c * 8) * DD + dd;
    const float* vs = g_v2 + ((size_t)h * 128 + (size_t)c * 8) * DD + dd;
    float sk = 0.f, sv = 0.f;
#pragma unroll
    for (int r = 0; r < 8; r++) { sk += ks[r * DD]; sv += vs[r * DD]; }
    g_k3[idx] = sk * 0.125f;
    g_v3[idx] = sv * 0.125f;
}

// ---------------- attention ----------------
// Pair-split design: threads 2t, 2t+1 co-own query (qs + t).
// Even lane holds d[0:32), odd lane d[32:64) of q and o.
// Per key: each lane does an 8xfloat4 half-dot, combines via shfl_xor(1),
// then both lanes update m/l (bit-identical) and their own o-half.

__global__ void __launch_bounds__(256, 2) attn_kernel(
    const float* __restrict__ q, const float* __restrict__ k,
    const float* __restrict__ v, const float* __restrict__ gammas,
    float* __restrict__ out)
{
    __shared__ float4 ksh[TS * 16];
    __shared__ float4 vsh[TS * 16];

    int h = blockIdx.y;
    // Reverse mapping: heavy (high-qs, triangular) tiles launch first.
    int qtile = (int)(gridDim.x - 1u - blockIdx.x);
    int qs = qtile * 128;
    int tid = threadIdx.x;
    int qi = qs + (tid >> 1);     // this pair's query index
    int half = tid & 1;           // 0: d[0:32), 1: d[32:64)

    float4 qr[8];
    {
        const float4* qg = reinterpret_cast<const float4*>(
            q + ((size_t)h * NN + qi) * DD + half * 32);
#pragma unroll
        for (int t = 0; t < 8; t++) qr[t] = qg[t];
    }

    float m = NEGINF, l = 0.f;
    float o[32];
#pragma unroll
    for (int t = 0; t < 32; t++) o[t] = 0.f;

    const float scale = 0.125f;

    // ---- Level 0: sliding window, keys [qs-128, qs+127], nearest-first ----
    {
        float g0 = gammas[0];
#pragma unroll 1
        for (int tb = qs + 128 - TS; tb >= qs - 128; tb -= TS) {
            __syncthreads();
            for (int e = tid; e < TS * 16; e += 256) {
                int row = e >> 4, col = e & 15;
                int j = tb + row;
                float4 kk = make_float4(0.f, 0.f, 0.f, 0.f), vv = kk;
                if (j >= 0) {
                    kk = reinterpret_cast<const float4*>(k + ((size_t)h * NN + j) * DD)[col];
                    vv = reinterpret_cast<const float4*>(v + ((size_t)h * NN + j) * DD)[col];
                }
                ksh[e] = kk; vsh[e] = vv;
            }
            __syncthreads();
#pragma unroll 1
            for (int r = TS - 1; r >= 0; r--) {
                int j = tb + r;
                int dist = qi - j;
                // half-dot (uniform control flow up through the shfl)
                const float4* krow = &ksh[r * 16 + half * 8];
                float a0 = 0.f, a1 = 0.f, a2 = 0.f, a3 = 0.f;
#pragma unroll
                for (int t = 0; t < 8; t++) {
                    float4 kk = krow[t];
                    a0 = fmaf(qr[t].x, kk.x, a0);
                    a1 = fmaf(qr[t].y, kk.y, a1);
                    a2 = fmaf(qr[t].z, kk.z, a2);
                    a3 = fmaf(qr[t].w, kk.w, a3);
                }
                float partial = (a0 + a1) + (a2 + a3);
                float full = partial + __shfl_xor_sync(0xffffffffu, partial, 1);
                float sc = fmaf(full, scale, -g0 * (float)dist);
                bool vis = (j >= 0) & (dist >= 0) & (dist <= WW - 1);
                if (vis) {
                    const float4* vrow = &vsh[r * 16 + half * 8];
                    if (sc <= m) {
                        float p = __expf(sc - m);
                        l += p;
#pragma unroll
                        for (int t = 0; t < 8; t++) {
                            float4 vv = vrow[t];
                            o[4 * t + 0] = fmaf(p, vv.x, o[4 * t + 0]);
                            o[4 * t + 1] = fmaf(p, vv.y, o[4 * t + 1]);
                            o[4 * t + 2] = fmaf(p, vv.z, o[4 * t + 2]);
                            o[4 * t + 3] = fmaf(p, vv.w, o[4 * t + 3]);
                        }
                    } else {
                        float c0 = __expf(m - sc);
                        m = sc;
                        l = fmaf(l, c0, 1.f);
#pragma unroll
                        for (int t = 0; t < 8; t++) {
                            float4 vv = vrow[t];
                            o[4 * t + 0] = fmaf(o[4 * t + 0], c0, vv.x);
                            o[4 * t + 1] = fmaf(o[4 * t + 1], c0, vv.y);
                            o[4 * t + 2] = fmaf(o[4 * t + 2], c0, vv.z);
                            o[4 * t + 3] = fmaf(o[4 * t + 3], c0, vv.w);
                        }
                    }
                }
            }
        }
    }

    // ---- Levels 1..3: pooled chunks, nearest-first ----
#pragma unroll 1
    for (int lvl = 1; lvl <= 3; lvl++) {
        const float* kl; const float* vl; int C, S;
        if (lvl == 1)      { kl = g_k1 + (size_t)h * 1024 * DD; vl = g_v1 + (size_t)h * 1024 * DD; C = 1024; S = 8;   }
        else if (lvl == 2) { kl = g_k2 + (size_t)h * 128  * DD; vl = g_v2 + (size_t)h * 128  * DD; C = 128;  S = 64;  }
        else               { kl = g_k3 + (size_t)h * 16   * DD; vl = g_v3 + (size_t)h * 16   * DD; C = 16;   S = 512; }
        float g = gammas[lvl];
        // bound for the block's max query (qi = qs+127): c <= qs/S - 1
        int cmax_blk = qs / S - 1;
        if (cmax_blk < 0) continue;
#pragma unroll 1
        for (int cb = (cmax_blk / TS) * TS; cb >= 0; cb -= TS) {
            __syncthreads();
            for (int e = tid; e < TS * 16; e += 256) {
                int row = e >> 4, col = e & 15;
                int c = cb + row;
                float4 kk = make_float4(0.f, 0.f, 0.f, 0.f), vv = kk;
                if (c < C) {
                    kk = reinterpret_cast<const float4*>(kl + (size_t)c * DD)[col];
                    vv = reinterpret_cast<const float4*>(vl + (size_t)c * DD)[col];
                }
                ksh[e] = kk; vsh[e] = vv;
            }
            __syncthreads();
#pragma unroll 1
            for (int r = TS - 1; r >= 0; r--) {
                int c = cb + r;
                int jlast = (c + 1) * S - 1;
                int dist = qi - jlast;
                const float4* krow = &ksh[r * 16 + half * 8];
                float a0 = 0.f, a1 = 0.f, a2 = 0.f, a3 = 0.f;
#pragma unroll
                for (int t = 0; t < 8; t++) {
                    float4 kk = krow[t];
                    a0 = fmaf(qr[t].x, kk.x, a0);
                    a1 = fmaf(qr[t].y, kk.y, a1);
                    a2 = fmaf(qr[t].z, kk.z, a2);
                    a3 = fmaf(qr[t].w, kk.w, a3);
                }
                float partial = (a0 + a1) + (a2 + a3);
                float full = partial + __shfl_xor_sync(0xffffffffu, partial, 1);
                float sc = fmaf(full, scale, -g * (float)dist);
                bool vis = (dist >= WW);   // c < C guaranteed by cb range
                if (vis) {
                    const float4* vrow = &vsh[r * 16 + half * 8];
                    if (sc <= m) {
                        float p = __expf(sc - m);
                        l += p;
#pragma unroll
                        for (int t = 0; t < 8; t++) {
                            float4 vv = vrow[t];
                            o[4 * t + 0] = fmaf(p, vv.x, o[4 * t + 0]);
                            o[4 * t + 1] = fmaf(p, vv.y, o[4 * t + 1]);
                            o[4 * t + 2] = fmaf(p, vv.z, o[4 * t + 2]);
                            o[4 * t + 3] = fmaf(p, vv.w, o[4 * t + 3]);
                        }
                    } else {
                        float c0 = __expf(m - sc);
                        m = sc;
                        l = fmaf(l, c0, 1.f);
#pragma unroll
                        for (int t = 0; t < 8; t++) {
                            float4 vv = vrow[t];
                            o[4 * t + 0] = fmaf(o[4 * t + 0], c0, vv.x);
                            o[4 * t + 1] = fmaf(o[4 * t + 1], c0, vv.y);
                            o[4 * t + 2] = fmaf(o[4 * t + 2], c0, vv.z);
                            o[4 * t + 3] = fmaf(o[4 * t + 3], c0, vv.w);
                        }
                    }
                }
            }
        }
    }

    // ---- write out = o / clip(l, 1e-8), each lane writes its d-half ----
    float inv = 1.0f / fmaxf(l, 1e-8f);
    float4* og = reinterpret_cast<float4*>(out + ((size_t)h * NN + qi) * DD + half * 32);
#pragma unroll
    for (int t = 0; t < 8; t++) {
        og[t] = make_float4(o[4 * t + 0] * inv, o[4 * t + 1] * inv,
                            o[4 * t + 2] * inv, o[4 * t + 3] * inv);
    }
}

// ---------------- launch ----------------
extern "C" void kernel_launch(void* const* d_in, const int* in_sizes, int n_in,
                              void* d_out, int out_size) {
    const float* q      = (const float*)d_in[0];
    const float* k      = (const float*)d_in[1];
    const float* v      = (const float*)d_in[2];
    const float* gammas = (const float*)d_in[3];
    float* out = (float*)d_out;

    pool1_kernel<<<(HH * 1024 * DD + 255) / 256, 256>>>(k, v);
    pool2_kernel<<<(HH * 128 * DD + 255) / 256, 256>>>();
    pool3_kernel<<<(HH * 16 * DD + 255) / 256, 256>>>();

    dim3 grid(NN / 128, HH);
    attn_kernel<<<grid, 256>>>(q, k, v, gammas, out);
}

// round 5
// speedup vs baseline: 1.6096x; 1.6096x over previous
#include <cuda_runtime.h>

#define HH 16
#define NN 8192
#define DD 64
#define WW 128
#define TS 64
#define NEGINF (-1e30f)

typedef unsigned long long u64;

// Pooled K/V scratch (allocation-free: __device__ globals)
__device__ float g_k1[HH * 1024 * DD];
__device__ float g_v1[HH * 1024 * DD];
__device__ float g_k2[HH * 128 * DD];
__device__ float g_v2[HH * 128 * DD];
__device__ float g_k3[HH * 16 * DD];
__device__ float g_v3[HH * 16 * DD];

// ---------------- packed f32x2 helpers (Blackwell) ----------------
__device__ __forceinline__ void ffma2(u64& acc, u64 a, u64 b) {
    asm("fma.rn.f32x2 %0, %1, %2, %0;" : "+l"(acc) : "l"(a), "l"(b));
}
// acc = acc * a + b
__device__ __forceinline__ void fmul_add2(u64& acc, u64 a, u64 b) {
    asm("fma.rn.f32x2 %0, %0, %1, %2;" : "+l"(acc) : "l"(a), "l"(b));
}
__device__ __forceinline__ u64 mul2(u64 a, u64 b) {
    u64 r; asm("mul.rn.f32x2 %0, %1, %2;" : "=l"(r) : "l"(a), "l"(b)); return r;
}
__device__ __forceinline__ u64 pack2(float x) {
    u64 r; asm("mov.b64 %0, {%1, %1};" : "=l"(r) : "f"(x)); return r;
}
__device__ __forceinline__ float2 unpack2(u64 v) {
    float lo, hi; asm("mov.b64 {%0, %1}, %2;" : "=f"(lo), "=f"(hi) : "l"(v));
    return make_float2(lo, hi);
}

// ---------------- pooling kernels ----------------
__global__ void pool1_kernel(const float* __restrict__ k, const float* __restrict__ v) {
    int idx = blockIdx.x * blockDim.x + threadIdx.x;
    if (idx >= HH * 1024 * DD) return;
    int dd = idx & (DD - 1);
    int c  = (idx / DD) & 1023;
    int h  = idx / (DD * 1024);
    const float* ks = k + ((size_t)h * NN + (size_t)c * 8) * DD + dd;
    const float* vs = v + ((size_t)h * NN + (size_t)c * 8) * DD + dd;
    float sk = 0.f, sv = 0.f;
#pragma unroll
    for (int r = 0; r < 8; r++) { sk += ks[r * DD]; sv += vs[r * DD]; }
    g_k1[idx] = sk * 0.125f;
    g_v1[idx] = sv * 0.125f;
}

__global__ void pool2_kernel() {
    int idx = blockIdx.x * blockDim.x + threadIdx.x;
    if (idx >= HH * 128 * DD) return;
    int dd = idx & (DD - 1);
    int c  = (idx / DD) & 127;
    int h  = idx / (DD * 128);
    const float* ks = g_k1 + ((size_t)h * 1024 + (size_t)c * 8) * DD + dd;
    const float* vs = g_v1 + ((size_t)h * 1024 + (size_t)c * 8) * DD + dd;
    float sk = 0.f, sv = 0.f;
#pragma unroll
    for (int r = 0; r < 8; r++) { sk += ks[r * DD]; sv += vs[r * DD]; }
    g_k2[idx] = sk * 0.125f;
    g_v2[idx] = sv * 0.125f;
}

__global__ void pool3_kernel() {
    int idx = blockIdx.x * blockDim.x + threadIdx.x;
    if (idx >= HH * 16 * DD) return;
    int dd = idx & (DD - 1);
    int c  = (idx / DD) & 15;
    int h  = idx / (DD * 16);
    const float* ks = g_k2 + ((size_t)h * 128 + (size_t)c * 8) * DD + dd;
    const float* vs = g_v2 + ((size_t)h * 128 + (size_t)c * 8) * DD + dd;
    float sk = 0.f, sv = 0.f;
#pragma unroll
    for (int r = 0; r < 8; r++) { sk += ks[r * DD]; sv += vs[r * DD]; }
    g_k3[idx] = sk * 0.125f;
    g_v3[idx] = sv * 0.125f;
}

// ---------------- attention ----------------
// Pair-split over d with INTERLEAVED smem rows:
//   global float4 index g (0..15) of a row is stored at position 2*(g&7)+(g>>3).
//   Even lane (half=0) reads positions 0,2,..,14; odd lane 1,3,..,15.
//   The two lanes of a pair hit adjacent 16B -> different banks -> 1 wavefront.
// Math is packed f32x2 (exact fp32, 2 FMAs per instruction).

// Row loader: e indexes (row, g). Stores float4 at interleaved position.
#define STORE_ROW(sh, src4, row, g) \
    (sh)[(row) * 16 + 2 * ((g) & 7) + ((g) >> 3)] = (src4)

__global__ void __launch_bounds__(256, 2) attn_kernel(
    const float* __restrict__ q, const float* __restrict__ k,
    const float* __restrict__ v, const float* __restrict__ gammas,
    float* __restrict__ out)
{
    __shared__ float4 ksh[TS * 16];
    __shared__ float4 vsh[TS * 16];

    int h = blockIdx.y;
    // Reverse mapping: heavy (high-qs, triangular) tiles launch first.
    int qtile = (int)(gridDim.x - 1u - blockIdx.x);
    int qs = qtile * 128;
    int tid = threadIdx.x;
    int qi = qs + (tid >> 1);     // this pair's query index
    int half = tid & 1;           // 0: d[0:32), 1: d[32:64)

    // q half in packed form: 8 x ulonglong2 (16 packed f32x2 values)
    ulonglong2 qp[8];
    {
        const ulonglong2* qg = reinterpret_cast<const ulonglong2*>(
            q + ((size_t)h * NN + qi) * DD + half * 32);
#pragma unroll
        for (int t = 0; t < 8; t++) qp[t] = qg[t];
    }

    float m = NEGINF, l = 0.f;
    u64 o2[16];
#pragma unroll
    for (int t = 0; t < 16; t++) o2[t] = 0ull;

    const float scale = 0.125f;
    const ulonglong2* ksh2 = reinterpret_cast<const ulonglong2*>(ksh);
    const ulonglong2* vsh2 = reinterpret_cast<const ulonglong2*>(vsh);

    // ---- Level 0: sliding window, keys [qs-128, qs+127], nearest-first ----
    {
        float g0 = gammas[0];
#pragma unroll 1
        for (int tb = qs + 128 - TS; tb >= qs - 128; tb -= TS) {
            __syncthreads();
            for (int e = tid; e < TS * 16; e += 256) {
                int row = e >> 4, g = e & 15;
                int j = tb + row;
                float4 kk = make_float4(0.f, 0.f, 0.f, 0.f), vv = kk;
                if (j >= 0) {
                    kk = reinterpret_cast<const float4*>(k + ((size_t)h * NN + j) * DD)[g];
                    vv = reinterpret_cast<const float4*>(v + ((size_t)h * NN + j) * DD)[g];
                }
                STORE_ROW(ksh, kk, row, g);
                STORE_ROW(vsh, vv, row, g);
            }
            __syncthreads();
#pragma unroll 1
            for (int r = TS - 1; r >= 0; r--) {
                int j = tb + r;
                int dist = qi - j;
                const ulonglong2* kr = ksh2 + (r * 16 + half);
                u64 a0 = 0ull, a1 = 0ull;
#pragma unroll
                for (int t = 0; t < 8; t++) {
                    ulonglong2 kk = kr[2 * t];
                    ffma2(a0, qp[t].x, kk.x);
                    ffma2(a1, qp[t].y, kk.y);
                }
                float2 f0 = unpack2(a0), f1 = unpack2(a1);
                float partial = (f0.x + f0.y) + (f1.x + f1.y);
                float full = partial + __shfl_xor_sync(0xffffffffu, partial, 1);
                float sc = fmaf(full, scale, -g0 * (float)dist);
                bool vis = (j >= 0) & (dist >= 0) & (dist <= WW - 1);
                if (vis) {
                    const ulonglong2* vr = vsh2 + (r * 16 + half);
                    if (sc <= m) {
                        float p = __expf(sc - m);
                        l += p;
                        u64 p2 = pack2(p);
#pragma unroll
                        for (int t = 0; t < 8; t++) {
                            ulonglong2 vv = vr[2 * t];
                            ffma2(o2[2 * t], p2, vv.x);
                            ffma2(o2[2 * t + 1], p2, vv.y);
                        }
                    } else {
                        float c0 = __expf(m - sc);
                        m = sc;
                        l = fmaf(l, c0, 1.f);
                        u64 c2 = pack2(c0);
#pragma unroll
                        for (int t = 0; t < 8; t++) {
                            ulonglong2 vv = vr[2 * t];
                            fmul_add2(o2[2 * t], c2, vv.x);
                            fmul_add2(o2[2 * t + 1], c2, vv.y);
                        }
                    }
                }
            }
        }
    }

    // ---- Levels 1..3: pooled chunks, nearest-first ----
#pragma unroll 1
    for (int lvl = 1; lvl <= 3; lvl++) {
        const float* kl; const float* vl; int C, S;
        if (lvl == 1)      { kl = g_k1 + (size_t)h * 1024 * DD; vl = g_v1 + (size_t)h * 1024 * DD; C = 1024; S = 8;   }
        else if (lvl == 2) { kl = g_k2 + (size_t)h * 128  * DD; vl = g_v2 + (size_t)h * 128  * DD; C = 128;  S = 64;  }
        else               { kl = g_k3 + (size_t)h * 16   * DD; vl = g_v3 + (size_t)h * 16   * DD; C = 16;   S = 512; }
        float g = gammas[lvl];
        // bound for the block's max query (qi = qs+127): c <= qs/S - 1
        int cmax_blk = qs / S - 1;
        if (cmax_blk < 0) continue;
#pragma unroll 1
        for (int cb = (cmax_blk / TS) * TS; cb >= 0; cb -= TS) {
            __syncthreads();
            for (int e = tid; e < TS * 16; e += 256) {
                int row = e >> 4, gg = e & 15;
                int c = cb + row;
                float4 kk = make_float4(0.f, 0.f, 0.f, 0.f), vv = kk;
                if (c < C) {
                    kk = reinterpret_cast<const float4*>(kl + (size_t)c * DD)[gg];
                    vv = reinterpret_cast<const float4*>(vl + (size_t)c * DD)[gg];
                }
                STORE_ROW(ksh, kk, row, gg);
                STORE_ROW(vsh, vv, row, gg);
            }
            __syncthreads();
#pragma unroll 1
            for (int r = TS - 1; r >= 0; r--) {
                int c = cb + r;
                int jlast = (c + 1) * S - 1;
                int dist = qi - jlast;
                const ulonglong2* kr = ksh2 + (r * 16 + half);
                u64 a0 = 0ull, a1 = 0ull;
#pragma unroll
                for (int t = 0; t < 8; t++) {
                    ulonglong2 kk = kr[2 * t];
                    ffma2(a0, qp[t].x, kk.x);
                    ffma2(a1, qp[t].y, kk.y);
                }
                float2 f0 = unpack2(a0), f1 = unpack2(a1);
                float partial = (f0.x + f0.y) + (f1.x + f1.y);
                float full = partial + __shfl_xor_sync(0xffffffffu, partial, 1);
                float sc = fmaf(full, scale, -g * (float)dist);
                bool vis = (dist >= WW);   // c < C guaranteed by cb range
                if (vis) {
                    const ulonglong2* vr = vsh2 + (r * 16 + half);
                    if (sc <= m) {
                        float p = __expf(sc - m);
                        l += p;
                        u64 p2 = pack2(p);
#pragma unroll
                        for (int t = 0; t < 8; t++) {
                            ulonglong2 vv = vr[2 * t];
                            ffma2(o2[2 * t], p2, vv.x);
                            ffma2(o2[2 * t + 1], p2, vv.y);
                        }
                    } else {
                        float c0 = __expf(m - sc);
                        m = sc;
                        l = fmaf(l, c0, 1.f);
                        u64 c2 = pack2(c0);
#pragma unroll
                        for (int t = 0; t < 8; t++) {
                            ulonglong2 vv = vr[2 * t];
                            fmul_add2(o2[2 * t], c2, vv.x);
                            fmul_add2(o2[2 * t + 1], c2, vv.y);
                        }
                    }
                }
            }
        }
    }

    // ---- write out = o / clip(l, 1e-8), each lane writes its d-half ----
    float inv = 1.0f / fmaxf(l, 1e-8f);
    u64 inv2 = pack2(inv);
    ulonglong2* og = reinterpret_cast<ulonglong2*>(out + ((size_t)h * NN + qi) * DD + half * 32);
#pragma unroll
    for (int t = 0; t < 8; t++) {
        ulonglong2 w;
        w.x = mul2(o2[2 * t], inv2);
        w.y = mul2(o2[2 * t + 1], inv2);
        og[t] = w;
    }
}

// ---------------- launch ----------------
extern "C" void kernel_launch(void* const* d_in, const int* in_sizes, int n_in,
                              void* d_out, int out_size) {
    const float* q      = (const float*)d_in[0];
    const float* k      = (const float*)d_in[1];
    const float* v      = (const float*)d_in[2];
    const float* gammas = (const float*)d_in[3];
    float* out = (float*)d_out;

    pool1_kernel<<<(HH * 1024 * DD + 255) / 256, 256>>>(k, v);
    pool2_kernel<<<(HH * 128 * DD + 255) / 256, 256>>>();
    pool3_kernel<<<(HH * 16 * DD + 255) / 256, 256>>>();

    dim3 grid(NN / 128, HH);
    attn_kernel<<<grid, 256>>>(q, k, v, gammas, out);
}